// round 9
// baseline (speedup 1.0000x reference)
#include <cuda_runtime.h>
#include <math.h>

#define NPTS 262144
#define NLVL 16
#define TSZ  (1u << 19)
#define TMASK (TSZ - 1u)
#define NTILES 2048
#define NCONS 148            // persistent MLP consumer CTAs (1 per SM)

typedef unsigned long long u64t;

__device__ __forceinline__ u64t pk2(float a, float b) {
    u64t r; asm("mov.b64 %0,{%1,%2};" : "=l"(r) : "f"(a), "f"(b)); return r;
}
__device__ __forceinline__ void upk2(u64t v, float& a, float& b) {
    asm("mov.b64 {%0,%1},%2;" : "=f"(a), "=f"(b) : "l"(v));
}
__device__ __forceinline__ void fma2(u64t& d, u64t a, u64t b) {
    asm("fma.rn.f32x2 %0,%1,%2,%0;" : "+l"(d) : "l"(a), "l"(b));
}

// ---------------------------------------------------------------------------
constexpr int OFF_SW0 = 0;            // 32*64
constexpr int OFF_SW1 = 2048;         // 64*64
constexpr int OFF_SW2 = 6144;         // 64*16
constexpr int OFF_CW0 = 7168;         // 42*64
constexpr int OFF_CW1 = 9856;         // 64*64
constexpr int OFF_CW2 = 13952;        // 64*3
constexpr int W_TOTAL = 14144;
__constant__ float c_w[W_TOTAL];

__constant__ int c_res[NLVL] = {16, 20, 25, 32, 40, 50, 64, 80,
                                101, 128, 161, 203, 256, 322, 406, 512};

// transposed hash features + per-tile ready flags
__device__ float g_feat[(size_t)32 * NPTS];
__device__ int   g_flag[NTILES];

constexpr int BP = 128;
constexpr int S  = 132;
constexpr int OFF_B0 = 0;
constexpr int OFF_B1 = 64 * S;
constexpr int SMEM_FLOATS = 2 * 64 * S;          // 16896
constexpr int SMEM_BYTES  = SMEM_FLOATS * 4;     // 67584

// ---------------------------------------------------------------------------
// R4's measured-good GEMM: warp -> 8 neurons, lane -> 4 points (2 f32x2 pairs)
// ---------------------------------------------------------------------------
template <int IN, bool RELU>
__device__ __forceinline__ void gemmC(const float* __restrict__ xb,
                                      float* __restrict__ yb,
                                      int woff, int warp, int lane)
{
    u64t acc[8][2];
    #pragma unroll
    for (int n = 0; n < 8; n++) { acc[n][0] = 0ull; acc[n][1] = 0ull; }

    const float* xr = xb + lane * 4;
    const int wb = woff + warp * 8;
    #pragma unroll 8
    for (int i = 0; i < IN; i++) {
        float4 xv = *(const float4*)(xr + i * S);
        u64t x01 = pk2(xv.x, xv.y);
        u64t x23 = pk2(xv.z, xv.w);
        float4 w0 = *(const float4*)(c_w + wb + i * 64);
        float4 w1 = *(const float4*)(c_w + wb + i * 64 + 4);
        u64t wd;
        wd = pk2(w0.x, w0.x); fma2(acc[0][0], x01, wd); fma2(acc[0][1], x23, wd);
        wd = pk2(w0.y, w0.y); fma2(acc[1][0], x01, wd); fma2(acc[1][1], x23, wd);
        wd = pk2(w0.z, w0.z); fma2(acc[2][0], x01, wd); fma2(acc[2][1], x23, wd);
        wd = pk2(w0.w, w0.w); fma2(acc[3][0], x01, wd); fma2(acc[3][1], x23, wd);
        wd = pk2(w1.x, w1.x); fma2(acc[4][0], x01, wd); fma2(acc[4][1], x23, wd);
        wd = pk2(w1.y, w1.y); fma2(acc[5][0], x01, wd); fma2(acc[5][1], x23, wd);
        wd = pk2(w1.z, w1.z); fma2(acc[6][0], x01, wd); fma2(acc[6][1], x23, wd);
        wd = pk2(w1.w, w1.w); fma2(acc[7][0], x01, wd); fma2(acc[7][1], x23, wd);
    }
    #pragma unroll
    for (int n = 0; n < 8; n++) {
        float a0, a1, a2, a3;
        upk2(acc[n][0], a0, a1);
        upk2(acc[n][1], a2, a3);
        if (RELU) {
            a0 = fmaxf(a0, 0.f); a1 = fmaxf(a1, 0.f);
            a2 = fmaxf(a2, 0.f); a3 = fmaxf(a3, 0.f);
        }
        *(float4*)(yb + (warp * 8 + n) * S + lane * 4) =
            make_float4(a0, a1, a2, a3);
    }
}

// sw2 GEMM (64 -> 16): warp -> 2 neurons
__device__ __forceinline__ void gemm16C(const float* __restrict__ xb,
                                        float* __restrict__ yb,
                                        int warp, int lane)
{
    u64t acc[2][2];
    acc[0][0] = acc[0][1] = acc[1][0] = acc[1][1] = 0ull;

    const float* xr = xb + lane * 4;
    const int wb = OFF_SW2 + warp * 2;
    #pragma unroll 8
    for (int i = 0; i < 64; i++) {
        float4 xv = *(const float4*)(xr + i * S);
        u64t x01 = pk2(xv.x, xv.y);
        u64t x23 = pk2(xv.z, xv.w);
        float2 wv = *(const float2*)(c_w + wb + i * 16);
        u64t wd;
        wd = pk2(wv.x, wv.x); fma2(acc[0][0], x01, wd); fma2(acc[0][1], x23, wd);
        wd = pk2(wv.y, wv.y); fma2(acc[1][0], x01, wd); fma2(acc[1][1], x23, wd);
    }
    #pragma unroll
    for (int n = 0; n < 2; n++) {
        float a0, a1, a2, a3;
        upk2(acc[n][0], a0, a1);
        upk2(acc[n][1], a2, a3);
        *(float4*)(yb + (warp * 2 + n) * S + lane * 4) =
            make_float4(a0, a1, a2, a3);
    }
}

// ---------------------------------------------------------------------------
// Producer: hash one tile (256 threads: 2 threads/point, 8 levels each),
// write transposed feats to gmem.  R4's measured-good hash body.
// ---------------------------------------------------------------------------
__device__ void hash_tile(const float* __restrict__ xyzt,
                          const float* __restrict__ table,
                          int t, int tid)
{
    const int p = tid & 127;
    const int lh = tid >> 7;                     // 0 or 1 (warp-uniform)
    const int gn = t * BP + p;
    float4 pt = *(const float4*)(xyzt + (size_t)gn * 4);

    #pragma unroll 1
    for (int k = 0; k < 8; k++) {
        const int l = 2 * k + lh;
        float r = (float)c_res[l];
        float px = pt.x * r, py = pt.y * r, pz = pt.z * r, pw = pt.w * r;
        float fx = floorf(px), fy = floorf(py), fz = floorf(pz), ft = floorf(pw);
        float wx = px - fx, wy = py - fy, wz = pz - fz, wt = pw - ft;
        unsigned cx = (unsigned)fx, cy = (unsigned)fy,
                 cz = (unsigned)fz, ct = (unsigned)ft;

        unsigned hx0 = cx,               hx1 = cx + 1u;
        unsigned hy0 = cy * 2654435761u, hy1 = (cy + 1u) * 2654435761u;
        unsigned hz0 = cz * 805459861u,  hz1 = (cz + 1u) * 805459861u;
        unsigned ht0 = ct * 3674653429u, ht1 = (ct + 1u) * 3674653429u;

        float wx0 = 1.f - wx, wy0 = 1.f - wy, wz0 = 1.f - wz, wt0 = 1.f - wt;

        const float2* tl = (const float2*)table + (size_t)l * TSZ;
        float a0 = 0.f, a1 = 0.f;

        if ((cx & 1u) == 0u) {
            const float4* t4 = (const float4*)tl;
            #pragma unroll
            for (int c8 = 0; c8 < 8; c8++) {
                unsigned hyy = (c8 & 1) ? hy1 : hy0;
                unsigned hzz = (c8 & 2) ? hz1 : hz0;
                unsigned htt = (c8 & 4) ? ht1 : ht0;
                unsigned idx0 = (hx0 ^ hyy ^ hzz ^ htt) & TMASK;
                float wyzt = ((c8 & 1) ? wy : wy0) * ((c8 & 2) ? wz : wz0) *
                             ((c8 & 4) ? wt : wt0);
                float w0 = wx0 * wyzt, w1 = wx * wyzt;
                float4 v = __ldg(&t4[idx0 >> 1]);
                bool hi = (idx0 & 1u);
                float f0x = hi ? v.z : v.x, f0y = hi ? v.w : v.y;
                float f1x = hi ? v.x : v.z, f1y = hi ? v.y : v.w;
                a0 = fmaf(f0x, w0, a0); a0 = fmaf(f1x, w1, a0);
                a1 = fmaf(f0y, w0, a1); a1 = fmaf(f1y, w1, a1);
            }
        } else {
            #pragma unroll
            for (int c8 = 0; c8 < 16; c8++) {
                unsigned hxx = (c8 & 1) ? hx1 : hx0;
                unsigned hyy = (c8 & 2) ? hy1 : hy0;
                unsigned hzz = (c8 & 4) ? hz1 : hz0;
                unsigned htt = (c8 & 8) ? ht1 : ht0;
                unsigned idx = (hxx ^ hyy ^ hzz ^ htt) & TMASK;
                float w = ((c8 & 1) ? wx : wx0) * ((c8 & 2) ? wy : wy0) *
                          ((c8 & 4) ? wz : wz0) * ((c8 & 8) ? wt : wt0);
                float2 f = __ldg(&tl[idx]);
                a0 = fmaf(f.x, w, a0);
                a1 = fmaf(f.y, w, a1);
            }
        }
        g_feat[(size_t)(2 * l + 0) * NPTS + gn] = a0;
        g_feat[(size_t)(2 * l + 1) * NPTS + gn] = a1;
    }
}

// ---------------------------------------------------------------------------
// Consumer: full MLP for one tile (256 threads).
// ---------------------------------------------------------------------------
__device__ void mlp_tile(float* __restrict__ s,
                         const float* __restrict__ dirs,
                         float* __restrict__ out,
                         int t, int warp, int lane, int tid)
{
    const int gbase = t * BP;

    // stage feats (transposed gmem -> rows of B0)
    #pragma unroll
    for (int r = 0; r < 4; r++) {
        int idx = tid + r * 256;          // 1024 float4s: 32 rows x 32 float4
        int i = idx >> 5, q = idx & 31;
        *(float4*)(s + OFF_B0 + i * S + q * 4) =
            *(const float4*)(g_feat + (size_t)i * NPTS + gbase + q * 4);
    }
    __syncthreads();

    gemmC<32, true>(s + OFF_B0, s + OFF_B1, OFF_SW0, warp, lane);
    __syncthreads();
    gemmC<64, true>(s + OFF_B1, s + OFF_B0, OFF_SW1, warp, lane);
    __syncthreads();
    gemm16C(s + OFF_B0, s + OFF_B1, warp, lane);       // h -> B1 rows 0..15
    __syncthreads();

    if (tid < BP) {
        const int p = tid;
        const int gn = gbase + p;
        float d0 = dirs[(size_t)gn * 3 + 0];
        float d1 = dirs[(size_t)gn * 3 + 1];
        float d2 = dirs[(size_t)gn * 3 + 2];
        s[OFF_B0 + 0 * S + p] = d0;
        s[OFF_B0 + 1 * S + p] = d1;
        s[OFF_B0 + 2 * S + p] = d2;
        float dd[3] = {d0, d1, d2};
        #pragma unroll
        for (int f = 0; f < 4; f++) {
            float fr = (float)(1 << f);
            #pragma unroll
            for (int c = 0; c < 3; c++) {
                float sv, cv;
                sincosf(dd[c] * fr, &sv, &cv);
                s[OFF_B0 + (3 + f * 3 + c) * S + p]  = sv;
                s[OFF_B0 + (15 + f * 3 + c) * S + p] = cv;
            }
        }
        #pragma unroll
        for (int k = 0; k < 15; k++)
            s[OFF_B0 + (27 + k) * S + p] = s[OFF_B1 + (1 + k) * S + p];
        out[gn] = s[OFF_B1 + 0 * S + p];               // sigma
    }
    __syncthreads();

    gemmC<42, true>(s + OFF_B0, s + OFF_B1, OFF_CW0, warp, lane);
    __syncthreads();
    gemmC<64, true>(s + OFF_B1, s + OFF_B0, OFF_CW1, warp, lane);
    __syncthreads();

    if (tid < BP) {
        const int p = tid;
        const int gn = gbase + p;
        float r0 = 0.f, r1 = 0.f, r2 = 0.f;
        #pragma unroll 8
        for (int i = 0; i < 64; i++) {
            float xv = s[OFF_B0 + i * S + p];
            r0 = fmaf(xv, c_w[OFF_CW2 + i * 3 + 0], r0);
            r1 = fmaf(xv, c_w[OFF_CW2 + i * 3 + 1], r1);
            r2 = fmaf(xv, c_w[OFF_CW2 + i * 3 + 2], r2);
        }
        out[(size_t)NPTS + (size_t)gn * 3 + 0] = 1.f / (1.f + __expf(-r0));
        out[(size_t)NPTS + (size_t)gn * 3 + 1] = 1.f / (1.f + __expf(-r1));
        out[(size_t)NPTS + (size_t)gn * 3 + 2] = 1.f / (1.f + __expf(-r2));
    }
    __syncthreads();     // B buffers reusable for next tile
}

// ---------------------------------------------------------------------------
// Kernel: CTAs 0..147 = persistent MLP consumers; CTAs 148+ = hash producers.
// ---------------------------------------------------------------------------
__global__ __launch_bounds__(256, 3) void fused_kernel(
    const float* __restrict__ xyzt,
    const float* __restrict__ dirs,
    const float* __restrict__ table,
    float* __restrict__ out)
{
    extern __shared__ float s[];
    const int tid = threadIdx.x;
    const int warp = tid >> 5, lane = tid & 31;
    const int bid = blockIdx.x;

    if (bid >= NCONS) {
        // ---- producer ----
        const int t = bid - NCONS;
        hash_tile(xyzt, table, t, tid);
        __syncthreads();
        __threadfence();
        if (tid == 0) atomicExch(&g_flag[t], 1);
    } else {
        // ---- persistent consumer ----
        for (int t = bid; t < NTILES; t += NCONS) {
            if (tid == 0) {
                while (atomicAdd(&g_flag[t], 0) == 0) { }
            }
            __syncthreads();
            __threadfence();        // acquire feats published by producer
            mlp_tile(s, dirs, out, t, warp, lane, tid);
        }
    }
}

// ---------------------------------------------------------------------------
extern "C" void kernel_launch(void* const* d_in, const int* in_sizes, int n_in,
                              void* d_out, int out_size)
{
    const float* xyzt  = (const float*)d_in[0];
    const float* dirs  = (const float*)d_in[1];
    const float* table = (const float*)d_in[2];

    cudaMemcpyToSymbolAsync(c_w, d_in[3], 2048 * 4, OFF_SW0 * 4,
                            cudaMemcpyDeviceToDevice);
    cudaMemcpyToSymbolAsync(c_w, d_in[4], 4096 * 4, OFF_SW1 * 4,
                            cudaMemcpyDeviceToDevice);
    cudaMemcpyToSymbolAsync(c_w, d_in[5], 1024 * 4, OFF_SW2 * 4,
                            cudaMemcpyDeviceToDevice);
    cudaMemcpyToSymbolAsync(c_w, d_in[6], 2688 * 4, OFF_CW0 * 4,
                            cudaMemcpyDeviceToDevice);
    cudaMemcpyToSymbolAsync(c_w, d_in[7], 4096 * 4, OFF_CW1 * 4,
                            cudaMemcpyDeviceToDevice);
    cudaMemcpyToSymbolAsync(c_w, d_in[8], 192 * 4, OFF_CW2 * 4,
                            cudaMemcpyDeviceToDevice);

    // clear per-tile flags (capturable async memset)
    void* flagp = nullptr;
    cudaGetSymbolAddress(&flagp, g_flag);
    cudaMemsetAsync(flagp, 0, NTILES * sizeof(int));

    cudaFuncSetAttribute(fused_kernel, cudaFuncAttributeMaxDynamicSharedMemorySize,
                         SMEM_BYTES);

    fused_kernel<<<NCONS + NTILES, 256, SMEM_BYTES>>>(xyzt, dirs, table,
                                                      (float*)d_out);
}

// round 10
// speedup vs baseline: 2.1527x; 2.1527x over previous
#include <cuda_runtime.h>
#include <math.h>

#define NPTS 262144
#define NLVL 16
#define TSZ  (1u << 19)
#define TMASK (TSZ - 1u)

typedef unsigned long long u64t;

__device__ __forceinline__ u64t pk2(float a, float b) {
    u64t r; asm("mov.b64 %0,{%1,%2};" : "=l"(r) : "f"(a), "f"(b)); return r;
}
__device__ __forceinline__ void upk2(u64t v, float& a, float& b) {
    asm("mov.b64 {%0,%1},%2;" : "=f"(a), "=f"(b) : "l"(v));
}
__device__ __forceinline__ void fma2(u64t& d, u64t a, u64t b) {
    asm("fma.rn.f32x2 %0,%1,%2,%0;" : "+l"(d) : "l"(a), "l"(b));
}

// ---------------------------------------------------------------------------
constexpr int OFF_SW0 = 0;            // 32*64
constexpr int OFF_SW1 = 2048;         // 64*64
constexpr int OFF_SW2 = 6144;         // 64*16
constexpr int OFF_CW0 = 7168;         // 42*64
constexpr int OFF_CW1 = 9856;         // 64*64
constexpr int OFF_CW2 = 13952;        // 64*3
constexpr int W_TOTAL = 14144;
__constant__ float c_w[W_TOTAL];

__constant__ int c_res[NLVL] = {16, 20, 25, 32, 40, 50, 64, 80,
                                101, 128, 161, 203, 256, 322, 406, 512};

constexpr int BP = 128;
constexpr int NT = 512;               // threads per CTA
constexpr int S  = 132;
constexpr int OFF_B0 = 0;
constexpr int OFF_B1 = 64 * S;
constexpr int SMEM_FLOATS = 2 * 64 * S;          // 16896
constexpr int SMEM_BYTES  = SMEM_FLOATS * 4;     // 67584

// ---------------------------------------------------------------------------
// GEMM: y[64][S] = act(W[IN][64]^T x[IN][S]).
// 16 warps x 4 neurons (1x LDC.128), lane -> 4 points (2 f32x2 pairs).
// ---------------------------------------------------------------------------
template <int IN, bool RELU>
__device__ __forceinline__ void gemmC(const float* __restrict__ xb,
                                      float* __restrict__ yb,
                                      int woff, int warp, int lane)
{
    u64t acc[4][2];
    #pragma unroll
    for (int n = 0; n < 4; n++) { acc[n][0] = 0ull; acc[n][1] = 0ull; }

    const float* xr = xb + lane * 4;
    const int wb = woff + warp * 4;
    #pragma unroll 8
    for (int i = 0; i < IN; i++) {
        float4 xv = *(const float4*)(xr + i * S);
        u64t x01 = pk2(xv.x, xv.y);
        u64t x23 = pk2(xv.z, xv.w);
        float4 w = *(const float4*)(c_w + wb + i * 64);
        u64t wd;
        wd = pk2(w.x, w.x); fma2(acc[0][0], x01, wd); fma2(acc[0][1], x23, wd);
        wd = pk2(w.y, w.y); fma2(acc[1][0], x01, wd); fma2(acc[1][1], x23, wd);
        wd = pk2(w.z, w.z); fma2(acc[2][0], x01, wd); fma2(acc[2][1], x23, wd);
        wd = pk2(w.w, w.w); fma2(acc[3][0], x01, wd); fma2(acc[3][1], x23, wd);
    }
    #pragma unroll
    for (int n = 0; n < 4; n++) {
        float a0, a1, a2, a3;
        upk2(acc[n][0], a0, a1);
        upk2(acc[n][1], a2, a3);
        if (RELU) {
            a0 = fmaxf(a0, 0.f); a1 = fmaxf(a1, 0.f);
            a2 = fmaxf(a2, 0.f); a3 = fmaxf(a3, 0.f);
        }
        *(float4*)(yb + (warp * 4 + n) * S + lane * 4) =
            make_float4(a0, a1, a2, a3);
    }
}

// sw2 GEMM (64 -> 16): 16 warps x 1 neuron
__device__ __forceinline__ void gemm16C(const float* __restrict__ xb,
                                        float* __restrict__ yb,
                                        int warp, int lane)
{
    u64t acc0 = 0ull, acc1 = 0ull;

    const float* xr = xb + lane * 4;
    #pragma unroll 8
    for (int i = 0; i < 64; i++) {
        float4 xv = *(const float4*)(xr + i * S);
        u64t x01 = pk2(xv.x, xv.y);
        u64t x23 = pk2(xv.z, xv.w);
        float wv = c_w[OFF_SW2 + i * 16 + warp];
        u64t wd = pk2(wv, wv);
        fma2(acc0, x01, wd);
        fma2(acc1, x23, wd);
    }
    float a0, a1, a2, a3;
    upk2(acc0, a0, a1);
    upk2(acc1, a2, a3);
    *(float4*)(yb + warp * S + lane * 4) = make_float4(a0, a1, a2, a3);
}

// ---------------------------------------------------------------------------
// Fused kernel: hash encode (-> smem) then MLPs. 128 points / block, 512 thr.
// ---------------------------------------------------------------------------
__global__ __launch_bounds__(NT, 2) void fused_kernel(
    const float* __restrict__ xyzt,
    const float* __restrict__ dirs,
    const float* __restrict__ table,
    float* __restrict__ out)
{
    extern __shared__ float s[];
    const int tid = threadIdx.x;
    const int warp = tid >> 5, lane = tid & 31;
    const int gbase = blockIdx.x * BP;

    // ---- stage xyzt into B1 (512 floats) ----
    if (tid < 512)
        s[OFF_B1 + tid] = xyzt[(size_t)gbase * 4 + tid];
    __syncthreads();

    // ---- hash phase: 4 threads per point, 4 levels each ----
    {
        const int p = tid & 127;
        const int lh = tid >> 7;                     // 0..3 (warp-uniform)
        float4 pt = *(const float4*)(s + OFF_B1 + p * 4);

        #pragma unroll 1
        for (int k = 0; k < 4; k++) {
            const int l = 4 * k + lh;
            float r = (float)c_res[l];
            float px = pt.x * r, py = pt.y * r, pz = pt.z * r, pw = pt.w * r;
            float fx = floorf(px), fy = floorf(py), fz = floorf(pz), ft = floorf(pw);
            float wx = px - fx, wy = py - fy, wz = pz - fz, wt = pw - ft;
            unsigned cx = (unsigned)fx, cy = (unsigned)fy,
                     cz = (unsigned)fz, ct = (unsigned)ft;

            unsigned hx0 = cx,               hx1 = cx + 1u;
            unsigned hy0 = cy * 2654435761u, hy1 = (cy + 1u) * 2654435761u;
            unsigned hz0 = cz * 805459861u,  hz1 = (cz + 1u) * 805459861u;
            unsigned ht0 = ct * 3674653429u, ht1 = (ct + 1u) * 3674653429u;

            float wx0 = 1.f - wx, wy0 = 1.f - wy, wz0 = 1.f - wz, wt0 = 1.f - wt;

            const float2* tl = (const float2*)table + (size_t)l * TSZ;
            float a0 = 0.f, a1 = 0.f;

            if ((cx & 1u) == 0u) {
                const float4* t4 = (const float4*)tl;
                #pragma unroll
                for (int c8 = 0; c8 < 8; c8++) {
                    unsigned hyy = (c8 & 1) ? hy1 : hy0;
                    unsigned hzz = (c8 & 2) ? hz1 : hz0;
                    unsigned htt = (c8 & 4) ? ht1 : ht0;
                    unsigned idx0 = (hx0 ^ hyy ^ hzz ^ htt) & TMASK;
                    float wyzt = ((c8 & 1) ? wy : wy0) * ((c8 & 2) ? wz : wz0) *
                                 ((c8 & 4) ? wt : wt0);
                    float w0 = wx0 * wyzt, w1 = wx * wyzt;
                    float4 v = __ldg(&t4[idx0 >> 1]);
                    bool hi = (idx0 & 1u);
                    float f0x = hi ? v.z : v.x, f0y = hi ? v.w : v.y;
                    float f1x = hi ? v.x : v.z, f1y = hi ? v.y : v.w;
                    a0 = fmaf(f0x, w0, a0); a0 = fmaf(f1x, w1, a0);
                    a1 = fmaf(f0y, w0, a1); a1 = fmaf(f1y, w1, a1);
                }
            } else {
                #pragma unroll
                for (int c8 = 0; c8 < 16; c8++) {
                    unsigned hxx = (c8 & 1) ? hx1 : hx0;
                    unsigned hyy = (c8 & 2) ? hy1 : hy0;
                    unsigned hzz = (c8 & 4) ? hz1 : hz0;
                    unsigned htt = (c8 & 8) ? ht1 : ht0;
                    unsigned idx = (hxx ^ hyy ^ hzz ^ htt) & TMASK;
                    float w = ((c8 & 1) ? wx : wx0) * ((c8 & 2) ? wy : wy0) *
                              ((c8 & 4) ? wz : wz0) * ((c8 & 8) ? wt : wt0);
                    float2 f = __ldg(&tl[idx]);
                    a0 = fmaf(f.x, w, a0);
                    a1 = fmaf(f.y, w, a1);
                }
            }
            s[OFF_B0 + (2 * l + 0) * S + p] = a0;
            s[OFF_B0 + (2 * l + 1) * S + p] = a1;
        }
    }
    __syncthreads();

    // ---- sigma net ----
    gemmC<32, true>(s + OFF_B0, s + OFF_B1, OFF_SW0, warp, lane);
    __syncthreads();
    gemmC<64, true>(s + OFF_B1, s + OFF_B0, OFF_SW1, warp, lane);
    __syncthreads();
    gemm16C(s + OFF_B0, s + OFF_B1, warp, lane);       // h -> B1 rows 0..15
    __syncthreads();

    // ---- color input assembly + sigma output ----
    if (tid < BP) {
        const int p = tid;
        const int gn = gbase + p;
        float d0 = dirs[(size_t)gn * 3 + 0];
        float d1 = dirs[(size_t)gn * 3 + 1];
        float d2 = dirs[(size_t)gn * 3 + 2];
        s[OFF_B0 + 0 * S + p] = d0;
        s[OFF_B0 + 1 * S + p] = d1;
        s[OFF_B0 + 2 * S + p] = d2;
        float dd[3] = {d0, d1, d2};
        #pragma unroll
        for (int f = 0; f < 4; f++) {
            float fr = (float)(1 << f);
            #pragma unroll
            for (int c = 0; c < 3; c++) {
                float ang = dd[c] * fr;
                s[OFF_B0 + (3 + f * 3 + c) * S + p]  = __sinf(ang);
                s[OFF_B0 + (15 + f * 3 + c) * S + p] = __cosf(ang);
            }
        }
        #pragma unroll
        for (int k = 0; k < 15; k++)
            s[OFF_B0 + (27 + k) * S + p] = s[OFF_B1 + (1 + k) * S + p];
        out[gn] = s[OFF_B1 + 0 * S + p];               // sigma
    }
    __syncthreads();

    // ---- color net ----
    gemmC<42, true>(s + OFF_B0, s + OFF_B1, OFF_CW0, warp, lane);
    __syncthreads();
    gemmC<64, true>(s + OFF_B1, s + OFF_B0, OFF_CW1, warp, lane);
    __syncthreads();

    // ---- final 64 -> 3 + sigmoid ----
    if (tid < BP) {
        const int p = tid;
        const int gn = gbase + p;
        float r0 = 0.f, r1 = 0.f, r2 = 0.f;
        #pragma unroll 8
        for (int i = 0; i < 64; i++) {
            float xv = s[OFF_B0 + i * S + p];
            r0 = fmaf(xv, c_w[OFF_CW2 + i * 3 + 0], r0);
            r1 = fmaf(xv, c_w[OFF_CW2 + i * 3 + 1], r1);
            r2 = fmaf(xv, c_w[OFF_CW2 + i * 3 + 2], r2);
        }
        out[(size_t)NPTS + (size_t)gn * 3 + 0] = 1.f / (1.f + __expf(-r0));
        out[(size_t)NPTS + (size_t)gn * 3 + 1] = 1.f / (1.f + __expf(-r1));
        out[(size_t)NPTS + (size_t)gn * 3 + 2] = 1.f / (1.f + __expf(-r2));
    }
}

// ---------------------------------------------------------------------------
extern "C" void kernel_launch(void* const* d_in, const int* in_sizes, int n_in,
                              void* d_out, int out_size)
{
    const float* xyzt  = (const float*)d_in[0];
    const float* dirs  = (const float*)d_in[1];
    const float* table = (const float*)d_in[2];

    cudaMemcpyToSymbolAsync(c_w, d_in[3], 2048 * 4, OFF_SW0 * 4,
                            cudaMemcpyDeviceToDevice);
    cudaMemcpyToSymbolAsync(c_w, d_in[4], 4096 * 4, OFF_SW1 * 4,
                            cudaMemcpyDeviceToDevice);
    cudaMemcpyToSymbolAsync(c_w, d_in[5], 1024 * 4, OFF_SW2 * 4,
                            cudaMemcpyDeviceToDevice);
    cudaMemcpyToSymbolAsync(c_w, d_in[6], 2688 * 4, OFF_CW0 * 4,
                            cudaMemcpyDeviceToDevice);
    cudaMemcpyToSymbolAsync(c_w, d_in[7], 4096 * 4, OFF_CW1 * 4,
                            cudaMemcpyDeviceToDevice);
    cudaMemcpyToSymbolAsync(c_w, d_in[8], 192 * 4, OFF_CW2 * 4,
                            cudaMemcpyDeviceToDevice);

    cudaFuncSetAttribute(fused_kernel, cudaFuncAttributeMaxDynamicSharedMemorySize,
                         SMEM_BYTES);

    fused_kernel<<<NPTS / BP, NT, SMEM_BYTES>>>(xyzt, dirs, table, (float*)d_out);
}